// round 3
// baseline (speedup 1.0000x reference)
#include <cuda_runtime.h>

// SuperVoxelLoss: mean( bce_with_logits(x,t) * (1 + 0.5*[(t>0.5) XOR (x>0)]) )
// Fused streaming reduction, unroll x8 for deep MLP. 128 MiB read, 4 B write.

#define NBLK 2048
#define NTHR 256
#define UNROLL 8

__device__ float g_partials[NBLK];
__device__ unsigned int g_ticket;   // zero-init; last block resets for graph replay

__device__ __forceinline__ float loss_elem(float x, float t) {
    // stable BCEWithLogits: max(x,0) - x*t + log(1 + exp(-|x|))
    float ax = fabsf(x);
    float e  = __expf(-ax);
    float l  = __logf(1.0f + e);
    float loss = fmaxf(x, 0.0f) - x * t + l;
    // pred_bin = (sigmoid(x) > 0.5) <=> (x > 0); masks are XOR of the bins
    bool pb = x > 0.0f;
    bool tb = t > 0.5f;
    float w = (pb != tb) ? 1.5f : 1.0f;
    return loss * w;
}

__device__ __forceinline__ float block_reduce(float v) {
    #pragma unroll
    for (int o = 16; o > 0; o >>= 1)
        v += __shfl_down_sync(0xFFFFFFFFu, v, o);

    __shared__ float s_warp[NTHR / 32];
    if ((threadIdx.x & 31) == 0) s_warp[threadIdx.x >> 5] = v;
    __syncthreads();

    if (threadIdx.x < 32) {
        float w = (threadIdx.x < NTHR / 32) ? s_warp[threadIdx.x] : 0.0f;
        #pragma unroll
        for (int o = 16; o > 0; o >>= 1)
            w += __shfl_down_sync(0xFFFFFFFFu, w, o);
        return w;   // valid in thread 0
    }
    return 0.0f;
}

__global__ void __launch_bounds__(NTHR)
svloss_fused_kernel(const float4* __restrict__ x4,
                    const float4* __restrict__ t4,
                    float* __restrict__ out,
                    int n4, float inv_n) {
    const int stride = gridDim.x * blockDim.x;
    const int tid = blockIdx.x * blockDim.x + threadIdx.x;

    float a0 = 0.0f, a1 = 0.0f, a2 = 0.0f, a3 = 0.0f;

    // Main body: UNROLL strided chunks, all loads front-batchable.
    int base = tid;
    while (base + (UNROLL - 1) * stride < n4) {
        float4 xv[UNROLL], tv[UNROLL];
        #pragma unroll
        for (int k = 0; k < UNROLL; k++) {
            xv[k] = __ldcs(&x4[base + k * stride]);
            tv[k] = __ldcs(&t4[base + k * stride]);
        }
        #pragma unroll
        for (int k = 0; k < UNROLL; k++) {
            a0 += loss_elem(xv[k].x, tv[k].x);
            a1 += loss_elem(xv[k].y, tv[k].y);
            a2 += loss_elem(xv[k].z, tv[k].z);
            a3 += loss_elem(xv[k].w, tv[k].w);
        }
        base += UNROLL * stride;
    }
    // Tail (none at the benchmark shape, kept for generality).
    for (int i = base; i < n4; i += stride) {
        float4 xv = __ldcs(&x4[i]);
        float4 tv = __ldcs(&t4[i]);
        a0 += loss_elem(xv.x, tv.x);
        a1 += loss_elem(xv.y, tv.y);
        a2 += loss_elem(xv.z, tv.z);
        a3 += loss_elem(xv.w, tv.w);
    }

    float acc = (a0 + a1) + (a2 + a3);
    float bsum = block_reduce(acc);

    __shared__ bool s_last;
    if (threadIdx.x == 0) {
        g_partials[blockIdx.x] = bsum;
        __threadfence();
        unsigned int c = atomicAdd(&g_ticket, 1u);
        s_last = (c == (unsigned int)gridDim.x - 1u);
    }
    __syncthreads();

    if (s_last) {
        float v = 0.0f;
        #pragma unroll
        for (int i = threadIdx.x; i < NBLK; i += NTHR)
            v += g_partials[i];
        float total = block_reduce(v);
        if (threadIdx.x == 0) {
            out[0] = total * inv_n;
            g_ticket = 0u;   // reset for next graph replay
        }
    }
}

extern "C" void kernel_launch(void* const* d_in, const int* in_sizes, int n_in,
                              void* d_out, int out_size) {
    const float4* x4 = (const float4*)d_in[0];
    const float4* t4 = (const float4*)d_in[1];
    float* out = (float*)d_out;

    int n = in_sizes[0];          // 16,777,216
    int n4 = n >> 2;

    svloss_fused_kernel<<<NBLK, NTHR>>>(x4, t4, out, n4, 1.0f / (float)n);
}

// round 4
// speedup vs baseline: 1.0245x; 1.0245x over previous
#include <cuda_runtime.h>
#include <cstdint>

// SuperVoxelLoss: mean( bce_with_logits(x,t) * (1 + 0.5*[(t>0.5) XOR (x>0)]) )
// cp.async (LDGSTS) depth-4 per-thread pipeline -> guaranteed MLP without
// register pressure. Each thread stages & consumes its OWN 16B slots: no
// block barriers needed. 128 MiB read, 4 B write.

#define NBLK 2048
#define NTHR 256
#define STAGES 4

__device__ float g_partials[NBLK];
__device__ unsigned int g_ticket;   // zero-init; last block resets for graph replay

__device__ __forceinline__ float loss_elem(float x, float t) {
    // stable BCEWithLogits: max(x,0) - x*t + log(1 + exp(-|x|))
    float ax = fabsf(x);
    float e  = __expf(-ax);
    float l  = __logf(1.0f + e);
    float loss = fmaxf(x, 0.0f) - x * t + l;
    // pred_bin = (sigmoid(x) > 0.5) <=> (x > 0); masks are XOR of the bins
    bool pb = x > 0.0f;
    bool tb = t > 0.5f;
    float w = (pb != tb) ? 1.5f : 1.0f;
    return loss * w;
}

__device__ __forceinline__ float block_reduce(float v) {
    #pragma unroll
    for (int o = 16; o > 0; o >>= 1)
        v += __shfl_down_sync(0xFFFFFFFFu, v, o);

    __shared__ float s_warp[NTHR / 32];
    if ((threadIdx.x & 31) == 0) s_warp[threadIdx.x >> 5] = v;
    __syncthreads();

    if (threadIdx.x < 32) {
        float w = (threadIdx.x < NTHR / 32) ? s_warp[threadIdx.x] : 0.0f;
        #pragma unroll
        for (int o = 16; o > 0; o >>= 1)
            w += __shfl_down_sync(0xFFFFFFFFu, w, o);
        return w;   // valid in thread 0
    }
    return 0.0f;
}

__device__ __forceinline__ void cp_async16(uint32_t smem_addr, const void* gptr) {
    asm volatile("cp.async.cg.shared.global [%0], [%1], 16;\n"
                 :: "r"(smem_addr), "l"(gptr) : "memory");
}
__device__ __forceinline__ void cp_commit() {
    asm volatile("cp.async.commit_group;\n" ::: "memory");
}
__device__ __forceinline__ void cp_wait_allbutN() {
    asm volatile("cp.async.wait_group %0;\n" :: "n"(STAGES - 1) : "memory");
}

__global__ void __launch_bounds__(NTHR, 6)
svloss_fused_kernel(const float4* __restrict__ x4,
                    const float4* __restrict__ t4,
                    float* __restrict__ out,
                    int n4, float inv_n) {
    __shared__ float4 smx[STAGES * NTHR];
    __shared__ float4 smt[STAGES * NTHR];

    const int tid = threadIdx.x;
    const int stride = NBLK * NTHR;                 // float4 units
    const int base = blockIdx.x * NTHR + tid;       // block-contiguous tiles

    uint32_t sx_base = (uint32_t)__cvta_generic_to_shared(&smx[tid]);
    uint32_t st_base = (uint32_t)__cvta_generic_to_shared(&smt[tid]);

    // Prologue: prefetch STAGES tiles (one group per stage).
    #pragma unroll
    for (int s = 0; s < STAGES; s++) {
        int idx = base + s * stride;
        if (idx < n4) {
            cp_async16(sx_base + (uint32_t)(s * NTHR) * 16u, &x4[idx]);
            cp_async16(st_base + (uint32_t)(s * NTHR) * 16u, &t4[idx]);
        }
        cp_commit();
    }

    float a0 = 0.0f, a1 = 0.0f, a2 = 0.0f, a3 = 0.0f;

    int k = 0;
    int k_next = STAGES;
    // Block-uniform loop bound (per-thread validity guarded inside).
    while (blockIdx.x * NTHR + k * stride < n4) {
        cp_wait_allbutN();                          // stage (k % STAGES) ready
        int stage = k & (STAGES - 1);
        int idx = base + k * stride;
        if (idx < n4) {
            float4 xv = smx[stage * NTHR + tid];
            float4 tv = smt[stage * NTHR + tid];
            a0 += loss_elem(xv.x, tv.x);
            a1 += loss_elem(xv.y, tv.y);
            a2 += loss_elem(xv.z, tv.z);
            a3 += loss_elem(xv.w, tv.w);
        }
        // Prefetch into the stage we just consumed (compute above orders the
        // smem read well before this overwrite can land).
        {
            int idx2 = base + k_next * stride;
            int stage2 = k_next & (STAGES - 1);
            if (idx2 < n4) {
                cp_async16(sx_base + (uint32_t)(stage2 * NTHR) * 16u, &x4[idx2]);
                cp_async16(st_base + (uint32_t)(stage2 * NTHR) * 16u, &t4[idx2]);
            }
            cp_commit();
            k_next++;
        }
        k++;
    }

    float acc = (a0 + a1) + (a2 + a3);
    float bsum = block_reduce(acc);

    __shared__ bool s_last;
    if (threadIdx.x == 0) {
        g_partials[blockIdx.x] = bsum;
        __threadfence();
        unsigned int c = atomicAdd(&g_ticket, 1u);
        s_last = (c == (unsigned int)gridDim.x - 1u);
    }
    __syncthreads();

    if (s_last) {
        float v = 0.0f;
        #pragma unroll
        for (int i = threadIdx.x; i < NBLK; i += NTHR)
            v += g_partials[i];
        float total = block_reduce(v);
        if (threadIdx.x == 0) {
            out[0] = total * inv_n;
            g_ticket = 0u;   // reset for next graph replay
        }
    }
}

extern "C" void kernel_launch(void* const* d_in, const int* in_sizes, int n_in,
                              void* d_out, int out_size) {
    const float4* x4 = (const float4*)d_in[0];
    const float4* t4 = (const float4*)d_in[1];
    float* out = (float*)d_out;

    int n = in_sizes[0];          // 16,777,216
    int n4 = n >> 2;

    svloss_fused_kernel<<<NBLK, NTHR>>>(x4, t4, out, n4, 1.0f / (float)n);
}

// round 5
// speedup vs baseline: 1.1722x; 1.1441x over previous
#include <cuda_runtime.h>

// SuperVoxelLoss: mean( bce_with_logits(x,t) * (1 + 0.5*[(t>0.5) XOR (x>0)]) )
// Persistent single-wave streaming reduction: 888 CTAs (148 SM x 6) all
// resident from t=0 -> no partial-wave bandwidth tail. 128 MiB read, 4 B out.

#define NTHR 256
#define NBLK 888          // 148 SMs * 6 resident CTAs = exactly one wave

__device__ float g_partials[NBLK];
__device__ unsigned int g_ticket;   // zero-init; last block resets for graph replay

__device__ __forceinline__ float loss_elem(float x, float t) {
    // stable BCEWithLogits: max(x,0) - x*t + log(1 + exp(-|x|))
    float ax = fabsf(x);
    float e  = __expf(-ax);
    float l  = __logf(1.0f + e);
    float loss = fmaxf(x, 0.0f) - x * t + l;
    // pred_bin = (sigmoid(x) > 0.5) <=> (x > 0); masks are XOR of the bins
    bool pb = x > 0.0f;
    bool tb = t > 0.5f;
    float w = (pb != tb) ? 1.5f : 1.0f;
    return loss * w;
}

__device__ __forceinline__ float block_reduce(float v) {
    #pragma unroll
    for (int o = 16; o > 0; o >>= 1)
        v += __shfl_down_sync(0xFFFFFFFFu, v, o);

    __shared__ float s_warp[NTHR / 32];
    if ((threadIdx.x & 31) == 0) s_warp[threadIdx.x >> 5] = v;
    __syncthreads();

    if (threadIdx.x < 32) {
        float w = (threadIdx.x < NTHR / 32) ? s_warp[threadIdx.x] : 0.0f;
        #pragma unroll
        for (int o = 16; o > 0; o >>= 1)
            w += __shfl_down_sync(0xFFFFFFFFu, w, o);
        return w;   // valid in thread 0
    }
    return 0.0f;
}

__global__ void __launch_bounds__(NTHR, 6)
svloss_fused_kernel(const float4* __restrict__ x4,
                    const float4* __restrict__ t4,
                    float* __restrict__ out,
                    int n4, float inv_n) {
    const int stride = NBLK * NTHR;
    const int tid = blockIdx.x * NTHR + threadIdx.x;

    float a0 = 0.0f, a1 = 0.0f, a2 = 0.0f, a3 = 0.0f;

    #pragma unroll 4
    for (int i = tid; i < n4; i += stride) {
        float4 xv = __ldcs(&x4[i]);
        float4 tv = __ldcs(&t4[i]);
        a0 += loss_elem(xv.x, tv.x);
        a1 += loss_elem(xv.y, tv.y);
        a2 += loss_elem(xv.z, tv.z);
        a3 += loss_elem(xv.w, tv.w);
    }

    float acc = (a0 + a1) + (a2 + a3);
    float bsum = block_reduce(acc);

    __shared__ bool s_last;
    if (threadIdx.x == 0) {
        g_partials[blockIdx.x] = bsum;
        __threadfence();
        unsigned int c = atomicAdd(&g_ticket, 1u);
        s_last = (c == (unsigned int)gridDim.x - 1u);
    }
    __syncthreads();

    if (s_last) {
        // deterministic fixed-order reduce of all partials
        float v = 0.0f;
        for (int i = threadIdx.x; i < NBLK; i += NTHR)
            v += g_partials[i];
        float total = block_reduce(v);
        if (threadIdx.x == 0) {
            out[0] = total * inv_n;
            g_ticket = 0u;   // reset for next graph replay
        }
    }
}

extern "C" void kernel_launch(void* const* d_in, const int* in_sizes, int n_in,
                              void* d_out, int out_size) {
    const float4* x4 = (const float4*)d_in[0];
    const float4* t4 = (const float4*)d_in[1];
    float* out = (float*)d_out;

    int n = in_sizes[0];          // 16,777,216
    int n4 = n >> 2;

    svloss_fused_kernel<<<NBLK, NTHR>>>(x4, t4, out, n4, 1.0f / (float)n);
}